// round 10
// baseline (speedup 1.0000x reference)
#include <cuda_runtime.h>
#include <cuda_bf16.h>
#include <math.h>

// Quantized softmax (SoftmaxBernoulli2): rows of 2048 int32 in [-128,127].
// LUT[q] = clip(round(exp((q-255)*is)/es),0,255); idx = x - rowmax + 255 (in [0,255]);
// out = LUT[idx] / sum_row(LUT[idx]) as fp32.
//
// R10: fused single kernel + R6 body (best kernel time, 174.2us):
//  - per-CTA table via binary exponentiation (1 double exp), overlapped with priming
//  - thread-private cp.async staging (each thread copies exactly the 32B it reads
//    -> wait_group suffices, no buffer barriers), depth-3 ring
//  - 2-row software pipeline: max-chain(row j+1) overlaps gather+sum+store(row j)
//  - ONE __syncthreads per row. 6 CTAs/SM persistent.

#define ROW   2048
#define TPB   256
#define NWARP (TPB / 32)
#define NBUF  3

__device__ __forceinline__ void cp_async16(void* smem, const void* gmem) {
    unsigned saddr = (unsigned)__cvta_generic_to_shared(smem);
    asm volatile("cp.async.cg.shared.global [%0], [%1], 16;\n"
                 :: "r"(saddr), "l"(gmem) : "memory");
}
#define CP_COMMIT() asm volatile("cp.async.commit_group;\n" ::: "memory")
#define CP_WAIT1()  asm volatile("cp.async.wait_group 1;\n" ::: "memory")
#define CP_WAIT2()  asm volatile("cp.async.wait_group 2;\n" ::: "memory")

__global__ __launch_bounds__(TPB, 6) void softmax_bernoulli2_kernel(
    const int* __restrict__ x, float* __restrict__ out,
    const float* __restrict__ input_scale, const float* __restrict__ exp_scale,
    int n_rows) {
    __shared__ unsigned s_tab[64 * 32];    // replicated packed LUT, bank == lane
    __shared__ int s_buf[NBUF][ROW];       // staging ring; bytes are thread-private
    __shared__ int s_tmp[256];             // scalar table staging
    __shared__ double s_r2[8];             // r^(2^j), r = exp(-input_scale)
    __shared__ int s_max[2][NWARP];        // parity-double-buffered partials
    __shared__ int s_sum[2][NWARP];

    const int tid  = threadIdx.x;
    const int lane = tid & 31;
    const int warp = tid >> 5;
    const unsigned laneW = (unsigned)lane;

    const long long stride = gridDim.x;    // grid clamped to <= n_rows
    long long row = blockIdx.x;

    // ---- prime the ring FIRST: rows row, row+s, row+2s into bufs 0,1,2 ----
    #pragma unroll
    for (int j = 0; j < NBUF; j++) {
        long long rj = row + (long long)j * stride;
        if (rj >= n_rows) rj = row;        // clamped dummy load (data unused)
        const int* g = x + rj * ROW + tid * 4;
        cp_async16(&s_buf[j][tid * 4], g);
        cp_async16(&s_buf[j][1024 + tid * 4], g + 1024);
        CP_COMMIT();
    }

    // ---- table build (overlaps priming flight): exp((q-255)*is) = r^(255-q) ----
    if (tid == 0) {
        double r = exp(-(double)input_scale[0]);  // ONE double exp per CTA
        double p = r;
        #pragma unroll
        for (int j = 0; j < 8; j++) { s_r2[j] = p; p = p * p; }
    }
    __syncthreads();
    {
        double es = (double)exp_scale[0];
        int k = 255 - tid;                 // exponent, 0..255
        double t = 1.0;
        #pragma unroll
        for (int j = 0; j < 8; j++) if ((k >> j) & 1) t *= s_r2[j];
        double r = nearbyint(t / es);      // half-even, matches jnp.round
        r = fmin(fmax(r, 0.0), 255.0);
        s_tmp[tid] = (int)r;
    }
    __syncthreads();
    #pragma unroll
    for (int i = tid; i < 64 * 32; i += TPB) {
        int w4 = (i >> 5) << 2;
        s_tab[i] = (unsigned)s_tmp[w4] | ((unsigned)s_tmp[w4 + 1] << 8) |
                   ((unsigned)s_tmp[w4 + 2] << 16) | ((unsigned)s_tmp[w4 + 3] << 24);
    }

    // ---- prologue: max of first row (own bytes via wait_group, no barrier) ----
    CP_WAIT2();
    int4 a = *reinterpret_cast<const int4*>(&s_buf[0][tid * 4]);
    int4 b = *reinterpret_cast<const int4*>(&s_buf[0][1024 + tid * 4]);
    int v[8] = {a.x, a.y, a.z, a.w, b.x, b.y, b.z, b.w};
    {
        int m = v[0];
        #pragma unroll
        for (int k = 1; k < 8; k++) m = max(m, v[k]);
        #pragma unroll
        for (int o = 16; o > 0; o >>= 1) m = max(m, __shfl_xor_sync(0xFFFFFFFFu, m, o));
        if (lane == 0) s_max[0][warp] = m;
    }
    __syncthreads();                       // publishes prologue max + fences s_tab
    int xmax = s_max[0][0];
    #pragma unroll
    for (int w = 1; w < NWARP; w++) xmax = max(xmax, s_max[0][w]);
    int c = 255 - xmax;                    // idx = v + c in [0,255], no clip needed

    int slot = 0;
    int par  = 1;
    for (; row < n_rows; row += stride) {
        int nslot = slot + 1; if (nslot == NBUF) nslot = 0;

        // -- next row: load own bytes (wait_group only, no barrier) + max chain --
        CP_WAIT1();
        int4 na = *reinterpret_cast<const int4*>(&s_buf[nslot][tid * 4]);
        int4 nb = *reinterpret_cast<const int4*>(&s_buf[nslot][1024 + tid * 4]);
        int nm = max(max(max(na.x, na.y), max(na.z, na.w)),
                     max(max(nb.x, nb.y), max(nb.z, nb.w)));
        #pragma unroll
        for (int o = 16; o > 0; o >>= 1) nm = max(nm, __shfl_xor_sync(0xFFFFFFFFu, nm, o));
        if (lane == 0) s_max[par][warp] = nm;

        // -- current row: gather + sum chain (independent of max chain above) --
        int e[8];
        int sum = 0;
        #pragma unroll
        for (int k = 0; k < 8; k++) {
            unsigned idx = (unsigned)(v[k] + c);
            unsigned w = s_tab[((idx >> 2) << 5) + laneW];
            e[k] = (int)__byte_perm(w, 0, 0x4440u | (idx & 3u));
            sum += e[k];
        }
        #pragma unroll
        for (int o = 16; o > 0; o >>= 1) sum += __shfl_xor_sync(0xFFFFFFFFu, sum, o);
        if (lane == 0) s_sum[par][warp] = sum;

        // -- refill freed slot with row + 3*stride (thread-private bytes) --
        {
            long long pr = row + (long long)NBUF * stride;
            if (pr >= n_rows) pr = row;    // clamped dummy
            const int* g = x + pr * ROW + tid * 4;
            cp_async16(&s_buf[slot][tid * 4], g);
            cp_async16(&s_buf[slot][1024 + tid * 4], g + 1024);
            CP_COMMIT();
        }

        __syncthreads();                   // single barrier: max(next) + sum(cur)

        // -- finish current row: normalize + streaming stores --
        int total = s_sum[par][0];
        #pragma unroll
        for (int w = 1; w < NWARP; w++) total += s_sum[par][w];
        const float inv = 1.0f / (float)total;

        float4 o0, o1;
        o0.x = (float)e[0] * inv; o0.y = (float)e[1] * inv;
        o0.z = (float)e[2] * inv; o0.w = (float)e[3] * inv;
        o1.x = (float)e[4] * inv; o1.y = (float)e[5] * inv;
        o1.z = (float)e[6] * inv; o1.w = (float)e[7] * inv;
        float* ob = out + row * ROW;
        __stcs(reinterpret_cast<float4*>(ob) + tid, o0);
        __stcs(reinterpret_cast<float4*>(ob + 1024) + tid, o1);

        // -- rotate pipeline state --
        int xm = s_max[par][0];
        #pragma unroll
        for (int w = 1; w < NWARP; w++) xm = max(xm, s_max[par][w]);
        c = 255 - xm;
        v[0] = na.x; v[1] = na.y; v[2] = na.z; v[3] = na.w;
        v[4] = nb.x; v[5] = nb.y; v[6] = nb.z; v[7] = nb.w;
        slot = nslot;
        par ^= 1;
    }
}

extern "C" void kernel_launch(void* const* d_in, const int* in_sizes, int n_in,
                              void* d_out, int out_size) {
    const int* x             = (const int*)d_in[0];
    const float* input_scale = (const float*)d_in[1];
    const float* exp_scale   = (const float*)d_in[2];
    float* out = (float*)d_out;

    const int n_rows = in_sizes[0] / ROW;

    int nblocks = 152 * 6;                 // 6 CTAs/SM (~34KB smem)
    if (nblocks > n_rows) nblocks = n_rows;

    softmax_bernoulli2_kernel<<<nblocks, TPB>>>(x, out, input_scale, exp_scale, n_rows);
}

// round 11
// speedup vs baseline: 1.0649x; 1.0649x over previous
#include <cuda_runtime.h>
#include <cuda_bf16.h>
#include <math.h>

// Quantized softmax (SoftmaxBernoulli2): rows of 2048 int32 in [-128,127].
// LUT[q] = clip(round(exp((q-255)*is)/es),0,255); idx = x - rowmax + 255 (in [0,255]);
// out = LUT[idx] / sum_row(LUT[idx]) as fp32.
//
// R11 = R9 frame (fused single kernel, cp.async double-buffered staging, 8 CTAs/SM,
// shfl reductions, streaming stores) + micro-opts:
//  - LDS.U8 byte-addressed LUT gather (conflict-free: addr bits[6:2]==lane), no PRMT
//  - table build uses one reciprocal instead of 256 DDIVs per CTA
//  - binary-exponentiation table (1 double exp per CTA)

#define ROW   2048
#define TPB   256
#define VPT   8
#define NWARP (TPB / 32)

__device__ __forceinline__ void cp_async16(void* smem, const void* gmem) {
    unsigned saddr = (unsigned)__cvta_generic_to_shared(smem);
    asm volatile("cp.async.cg.shared.global [%0], [%1], 16;\n"
                 :: "r"(saddr), "l"(gmem) : "memory");
}
#define CP_COMMIT() asm volatile("cp.async.commit_group;\n" ::: "memory")
#define CP_WAIT1()  asm volatile("cp.async.wait_group 1;\n" ::: "memory")

__global__ __launch_bounds__(TPB, 8) void softmax_bernoulli2_kernel(
    const int* __restrict__ x, float* __restrict__ out,
    const float* __restrict__ input_scale, const float* __restrict__ exp_scale,
    int n_rows) {
    __shared__ unsigned s_tab[64 * 32];   // replicated packed LUT; gathered as bytes
    __shared__ int s_buf[2][ROW];         // double-buffered staged rows
    __shared__ int s_tmp[256];            // scalar table staging
    __shared__ double s_r2[9];            // [0..7]=r^(2^j), [8]=1/exp_scale
    __shared__ int s_max[NWARP];
    __shared__ int s_sum[NWARP];

    const int tid  = threadIdx.x;
    const int lane = tid & 31;
    const int warp = tid >> 5;

    const long long stride = gridDim.x;   // grid clamped to <= n_rows
    long long row = blockIdx.x;

    // ---- issue priming loads FIRST so they fly during the table build ----
    {
        const int* s0 = x + row * ROW + tid * 4;
        cp_async16(&s_buf[0][tid * 4], s0);
        cp_async16(&s_buf[0][1024 + tid * 4], s0 + 1024);
        CP_COMMIT();
        long long r1 = row + stride;
        if (r1 >= n_rows) r1 = row;       // clamped dummy
        const int* s1 = x + r1 * ROW + tid * 4;
        cp_async16(&s_buf[1][tid * 4], s1);
        cp_async16(&s_buf[1][1024 + tid * 4], s1 + 1024);
        CP_COMMIT();
    }

    // ---- table build: exp((q-255)*is) = r^(255-q), binary exponentiation ----
    if (tid == 0) {
        double r = exp(-(double)input_scale[0]);  // ONE double exp per CTA
        double p = r;
        #pragma unroll
        for (int j = 0; j < 8; j++) { s_r2[j] = p; p = p * p; }
        s_r2[8] = 1.0 / (double)exp_scale[0];     // one reciprocal, no per-thread DDIV
    }
    __syncthreads();
    {
        int k = 255 - tid;                // exponent, 0..255
        double t = s_r2[8];               // start from 1/es: t = r^k / es
        #pragma unroll
        for (int j = 0; j < 8; j++) if ((k >> j) & 1) t *= s_r2[j];
        double r = nearbyint(t);          // half-even, matches jnp.round
        r = fmin(fmax(r, 0.0), 255.0);
        s_tmp[tid] = (int)r;
    }
    __syncthreads();
    // pack 4 entries/word, replicate x32: word layout s_tab[word*32 + lane]
    #pragma unroll
    for (int i = tid; i < 64 * 32; i += TPB) {
        int w4 = (i >> 5) << 2;
        s_tab[i] = (unsigned)s_tmp[w4] | ((unsigned)s_tmp[w4 + 1] << 8) |
                   ((unsigned)s_tmp[w4 + 2] << 16) | ((unsigned)s_tmp[w4 + 3] << 24);
    }
    // (barrier A below fences s_tab before first gather)

    // Byte view base for this lane: entry idx lives at ((idx>>2)<<7) + (lane<<2) + (idx&3).
    // Address bits[6:2] == lane -> bank == lane, conflict-free LDS.U8.
    const unsigned char* tabB =
        reinterpret_cast<const unsigned char*>(s_tab) + (lane << 2);

    int p = 0;
    for (; row < n_rows; row += stride, p ^= 1) {
        CP_WAIT1();
        __syncthreads();                  // barrier A: buf[p] ready CTA-wide (+ LUT fence)

        int4 a = *reinterpret_cast<const int4*>(&s_buf[p][tid * 8]);
        int4 b = *reinterpret_cast<const int4*>(&s_buf[p][tid * 8 + 4]);
        int v[VPT] = {a.x, a.y, a.z, a.w, b.x, b.y, b.z, b.w};

        // ---- block max ----
        int m = v[0];
        #pragma unroll
        for (int k = 1; k < VPT; k++) m = max(m, v[k]);
        #pragma unroll
        for (int o = 16; o > 0; o >>= 1) m = max(m, __shfl_xor_sync(0xFFFFFFFFu, m, o));
        if (lane == 0) s_max[warp] = m;
        __syncthreads();                  // barrier B: max ready AND buf[p] consumed

        // ---- refill freed buffer with row + 2*stride (clamped) ----
        {
            long long pr = row + 2 * stride;
            if (pr >= n_rows) pr = row;   // clamped dummy
            const int* sp = x + pr * ROW + tid * 4;
            cp_async16(&s_buf[p][tid * 4], sp);
            cp_async16(&s_buf[p][1024 + tid * 4], sp + 1024);
            CP_COMMIT();
        }

        int xmax = s_max[0];
        #pragma unroll
        for (int w = 1; w < NWARP; w++) xmax = max(xmax, s_max[w]);
        const int c = 255 - xmax;         // idx = v + c in [0,255], no clip needed

        // ---- byte gather from LUT + exact int sum ----
        int e[VPT];
        int sum = 0;
        #pragma unroll
        for (int k = 0; k < VPT; k++) {
            unsigned idx = (unsigned)(v[k] + c);
            e[k] = (int)tabB[((idx >> 2) << 7) + (idx & 3u)];   // LDS.U8, bank==lane
            sum += e[k];
        }
        #pragma unroll
        for (int o = 16; o > 0; o >>= 1) sum += __shfl_xor_sync(0xFFFFFFFFu, sum, o);
        if (lane == 0) s_sum[warp] = sum;
        __syncthreads();                  // barrier C
        int total = s_sum[0];
        #pragma unroll
        for (int w = 1; w < NWARP; w++) total += s_sum[w];

        const float inv = 1.0f / (float)total;

        float4 o0, o1;
        o0.x = (float)e[0] * inv; o0.y = (float)e[1] * inv;
        o0.z = (float)e[2] * inv; o0.w = (float)e[3] * inv;
        o1.x = (float)e[4] * inv; o1.y = (float)e[5] * inv;
        o1.z = (float)e[6] * inv; o1.w = (float)e[7] * inv;
        float4* op = reinterpret_cast<float4*>(out + row * ROW) + tid * 2;
        __stcs(op, o0);                   // streaming stores: no reuse
        __stcs(op + 1, o1);
    }
}

extern "C" void kernel_launch(void* const* d_in, const int* in_sizes, int n_in,
                              void* d_out, int out_size) {
    const int* x             = (const int*)d_in[0];
    const float* input_scale = (const float*)d_in[1];
    const float* exp_scale   = (const float*)d_in[2];
    float* out = (float*)d_out;

    const int n_rows = in_sizes[0] / ROW;

    int nblocks = 152 * 8;                // 8 CTAs/SM (25.7KB smem, 32 regs)
    if (nblocks > n_rows) nblocks = n_rows;

    softmax_bernoulli2_kernel<<<nblocks, TPB>>>(x, out, input_scale, exp_scale, n_rows);
}

// round 12
// speedup vs baseline: 1.0923x; 1.0257x over previous
#include <cuda_runtime.h>
#include <cuda_bf16.h>
#include <math.h>

// Quantized softmax (SoftmaxBernoulli2): rows of 2048 int32 in [-128,127].
// LUT[q] = clip(round(exp((q-255)*is)/es),0,255); idx = x - rowmax + 255 (in [0,255]);
// out = LUT[idx] / sum_row(LUT[idx]) as fp32.
//
// R12 = R11 frame + speculative-max: gather+sum run with assumed xmax=127 (the int8
// upper bound) IN PARALLEL with the real max reduction; one barrier publishes both.
// If the true block max != 127 (rare, uniform across block -> no divergence), redo
// the gather with the true shift. 2 barriers/row instead of 3; max chain off the
// critical path. Fused table build, cp.async double buffering, byte-addressed
// conflict-free LUT (LDS.U8, bank==lane), 8 CTAs/SM.

#define ROW   2048
#define TPB   256
#define VPT   8
#define NWARP (TPB / 32)

__device__ __forceinline__ void cp_async16(void* smem, const void* gmem) {
    unsigned saddr = (unsigned)__cvta_generic_to_shared(smem);
    asm volatile("cp.async.cg.shared.global [%0], [%1], 16;\n"
                 :: "r"(saddr), "l"(gmem) : "memory");
}
#define CP_COMMIT() asm volatile("cp.async.commit_group;\n" ::: "memory")
#define CP_WAIT1()  asm volatile("cp.async.wait_group 1;\n" ::: "memory")

__global__ __launch_bounds__(TPB, 8) void softmax_bernoulli2_kernel(
    const int* __restrict__ x, float* __restrict__ out,
    const float* __restrict__ input_scale, const float* __restrict__ exp_scale,
    int n_rows) {
    __shared__ unsigned s_tab[64 * 32];   // replicated packed LUT; gathered as bytes
    __shared__ int s_buf[2][ROW];         // double-buffered staged rows
    __shared__ int s_tmp[256];            // scalar table staging
    __shared__ double s_r2[9];            // [0..7]=r^(2^j), [8]=1/exp_scale
    __shared__ int s_max[NWARP];
    __shared__ int s_sum[NWARP];
    __shared__ int s_sum2[NWARP];         // rare-path redo sums

    const int tid  = threadIdx.x;
    const int lane = tid & 31;
    const int warp = tid >> 5;

    const long long stride = gridDim.x;   // grid clamped to <= n_rows
    long long row = blockIdx.x;

    // ---- issue priming loads FIRST so they fly during the table build ----
    {
        const int* s0 = x + row * ROW + tid * 4;
        cp_async16(&s_buf[0][tid * 4], s0);
        cp_async16(&s_buf[0][1024 + tid * 4], s0 + 1024);
        CP_COMMIT();
        long long r1 = row + stride;
        if (r1 >= n_rows) r1 = row;       // clamped dummy
        const int* s1 = x + r1 * ROW + tid * 4;
        cp_async16(&s_buf[1][tid * 4], s1);
        cp_async16(&s_buf[1][1024 + tid * 4], s1 + 1024);
        CP_COMMIT();
    }

    // ---- table build: exp((q-255)*is) = r^(255-q), binary exponentiation ----
    if (tid == 0) {
        double r = exp(-(double)input_scale[0]);  // ONE double exp per CTA
        double p = r;
        #pragma unroll
        for (int j = 0; j < 8; j++) { s_r2[j] = p; p = p * p; }
        s_r2[8] = 1.0 / (double)exp_scale[0];
    }
    __syncthreads();
    {
        int k = 255 - tid;                // exponent, 0..255
        double t = s_r2[8];               // t = r^k / es
        #pragma unroll
        for (int j = 0; j < 8; j++) if ((k >> j) & 1) t *= s_r2[j];
        double r = nearbyint(t);          // half-even, matches jnp.round
        r = fmin(fmax(r, 0.0), 255.0);
        s_tmp[tid] = (int)r;
    }
    __syncthreads();
    #pragma unroll
    for (int i = tid; i < 64 * 32; i += TPB) {
        int w4 = (i >> 5) << 2;
        s_tab[i] = (unsigned)s_tmp[w4] | ((unsigned)s_tmp[w4 + 1] << 8) |
                   ((unsigned)s_tmp[w4 + 2] << 16) | ((unsigned)s_tmp[w4 + 3] << 24);
    }
    // (barrier A below fences s_tab before first gather)

    // Byte view: entry idx at ((idx>>2)<<7) + (lane<<2) + (idx&3); bits[6:2]==lane
    // -> bank == lane, conflict-free LDS.U8.
    const unsigned char* tabB =
        reinterpret_cast<const unsigned char*>(s_tab) + (lane << 2);

    int p = 0;
    for (; row < n_rows; row += stride, p ^= 1) {
        CP_WAIT1();
        __syncthreads();                  // barrier A: buf[p] ready CTA-wide (+ LUT fence)

        int4 a = *reinterpret_cast<const int4*>(&s_buf[p][tid * 8]);
        int4 b = *reinterpret_cast<const int4*>(&s_buf[p][tid * 8 + 4]);
        int v[VPT] = {a.x, a.y, a.z, a.w, b.x, b.y, b.z, b.w};

        // ---- max chain (independent of the speculative gather below) ----
        int m = v[0];
        #pragma unroll
        for (int k = 1; k < VPT; k++) m = max(m, v[k]);
        #pragma unroll
        for (int o = 16; o > 0; o >>= 1) m = max(m, __shfl_xor_sync(0xFFFFFFFFu, m, o));
        if (lane == 0) s_max[warp] = m;

        // ---- speculative gather assuming xmax == 127 (c = 128) + sum chain ----
        int e[VPT];
        int sum = 0;
        #pragma unroll
        for (int k = 0; k < VPT; k++) {
            unsigned idx = (unsigned)(v[k] + 128);            // in [0,255]
            e[k] = (int)tabB[((idx >> 2) << 7) + (idx & 3u)]; // LDS.U8, bank==lane
            sum += e[k];
        }
        #pragma unroll
        for (int o = 16; o > 0; o >>= 1) sum += __shfl_xor_sync(0xFFFFFFFFu, sum, o);
        if (lane == 0) s_sum[warp] = sum;

        // ---- refill freed buffer with row + 2*stride (clamped) ----
        {
            long long pr = row + 2 * stride;
            if (pr >= n_rows) pr = row;   // clamped dummy
            const int* sp = x + pr * ROW + tid * 4;
            cp_async16(&s_buf[p][tid * 4], sp);
            cp_async16(&s_buf[p][1024 + tid * 4], sp + 1024);
            CP_COMMIT();
        }

        __syncthreads();                  // barrier B: max + speculative sum published

        int xmax = s_max[0];
        #pragma unroll
        for (int w = 1; w < NWARP; w++) xmax = max(xmax, s_max[w]);

        int total;
        if (xmax == 127) {                // hot path (~99.97% of uniform rows)
            total = s_sum[0];
            #pragma unroll
            for (int w = 1; w < NWARP; w++) total += s_sum[w];
        } else {                          // cold path: uniform branch, always correct
            const int c = 255 - xmax;
            int sum2 = 0;
            #pragma unroll
            for (int k = 0; k < VPT; k++) {
                unsigned idx = (unsigned)(v[k] + c);          // in [0,255]
                e[k] = (int)tabB[((idx >> 2) << 7) + (idx & 3u)];
                sum2 += e[k];
            }
            #pragma unroll
            for (int o = 16; o > 0; o >>= 1) sum2 += __shfl_xor_sync(0xFFFFFFFFu, sum2, o);
            if (lane == 0) s_sum2[warp] = sum2;
            __syncthreads();              // whole block is here together
            total = s_sum2[0];
            #pragma unroll
            for (int w = 1; w < NWARP; w++) total += s_sum2[w];
        }

        const float inv = 1.0f / (float)total;

        float4 o0, o1;
        o0.x = (float)e[0] * inv; o0.y = (float)e[1] * inv;
        o0.z = (float)e[2] * inv; o0.w = (float)e[3] * inv;
        o1.x = (float)e[4] * inv; o1.y = (float)e[5] * inv;
        o1.z = (float)e[6] * inv; o1.w = (float)e[7] * inv;
        float4* op = reinterpret_cast<float4*>(out + row * ROW) + tid * 2;
        __stcs(op, o0);                   // streaming stores: no reuse
        __stcs(op + 1, o1);
    }
}

extern "C" void kernel_launch(void* const* d_in, const int* in_sizes, int n_in,
                              void* d_out, int out_size) {
    const int* x             = (const int*)d_in[0];
    const float* input_scale = (const float*)d_in[1];
    const float* exp_scale   = (const float*)d_in[2];
    float* out = (float*)d_out;

    const int n_rows = in_sizes[0] / ROW;

    int nblocks = 152 * 8;                // 8 CTAs/SM (25.8KB smem, ~32 regs)
    if (nblocks > n_rows) nblocks = n_rows;

    softmax_bernoulli2_kernel<<<nblocks, TPB>>>(x, out, input_scale, exp_scale, n_rows);
}